// round 14
// baseline (speedup 1.0000x reference)
#include <cuda_runtime.h>

#define NT 128
#define NH 8
#define NL 3
#define LOG2E 1.4426950408889634f

#define O_WK  0
#define O_WQ  24
#define O_WV  48
#define O_WP  72
#define O_BP  96
#define O_W1  99
#define O_B1  111
#define O_W2  123
#define O_B2  135
#define O_WLM 138
#define O_BLM 139
#define NWTS  140

__device__ __forceinline__ float ex2(float x) {
    float y;
    asm("ex2.approx.ftz.f32 %0, %1;" : "=f"(y) : "f"(x));
    return y;
}

__device__ __forceinline__ float redux_max_nn(float x) {
    unsigned r;
    asm("redux.sync.max.u32 %0, %1, 0xffffffff;" : "=r"(r) : "r"(__float_as_uint(x)));
    return __uint_as_float(r);
}
__device__ __forceinline__ float redux_min_nn(float x) {
    unsigned r;
    asm("redux.sync.min.u32 %0, %1, 0xffffffff;" : "=r"(r) : "r"(__float_as_uint(x)));
    return __uint_as_float(r);
}

struct OS { float m, d, n; };
__device__ __forceinline__ OS comb(OS a, OS b) {
    float mx = fmaxf(a.m, b.m);
    float mn = fminf(a.m, b.m);
    float e  = ex2(mn - mx);
    bool  bl = a.m < b.m;
    float sa = bl ? e : 1.0f;
    float sb = bl ? 1.0f : e;
    OS r; r.m = mx; r.d = fmaf(a.d, sa, b.d * sb); r.n = fmaf(a.n, sa, b.n * sb);
    return r;
}

// exact online-softmax exclusive-prefix scan (fallback, any range)
__device__ __forceinline__ void monoid_scan(
    float ch, float xx0, float xx1, float xx2, float xx3,
    float uu0, float uu1, float uu2, float uu3, int lid,
    float& h0, float& h1, float& h2, float& h3)
{
    OS a0 = { ch*uu0, 1.0f, xx0 };
    OS a1 = comb(a0, { ch*uu1, 1.0f, xx1 });
    OS a2 = comb(a1, { ch*uu2, 1.0f, xx2 });
    OS a3 = comb(a2, { ch*uu3, 1.0f, xx3 });
    OS agg = a3;
    #pragma unroll
    for (int o = 1; o < 32; o <<= 1) {
        OS up;
        up.m = __shfl_up_sync(0xffffffffu, agg.m, o);
        up.d = __shfl_up_sync(0xffffffffu, agg.d, o);
        up.n = __shfl_up_sync(0xffffffffu, agg.n, o);
        if (lid >= o) agg = comb(up, agg);
    }
    OS P;
    P.m = __shfl_up_sync(0xffffffffu, agg.m, 1);
    P.d = __shfl_up_sync(0xffffffffu, agg.d, 1);
    P.n = __shfl_up_sync(0xffffffffu, agg.n, 1);
    if (lid == 0) { P.m = -1e30f; P.d = 0.0f; P.n = 0.0f; }
    OS q1 = comb(P, a0);
    OS q2 = comb(P, a1);
    OS q3 = comb(P, a2);
    h0 = (lid == 0) ? 0.0f : __fdividef(P.n, P.d);
    h1 = __fdividef(q1.n, q1.d);
    h2 = __fdividef(q2.n, q2.d);
    h3 = __fdividef(q3.n, q3.d);
}

__global__ __launch_bounds__(128) void cat_kernel(
    const float* __restrict__ X,
    const float* __restrict__ wk, const float* __restrict__ wq, const float* __restrict__ wv,
    const float* __restrict__ Wp, const float* __restrict__ bp,
    const float* __restrict__ W1, const float* __restrict__ b1,
    const float* __restrict__ W2, const float* __restrict__ b2,
    const float* __restrict__ w_lm, const float* __restrict__ b_lm,
    float* __restrict__ out)
{
    __shared__ float W[NWTS];

    const int tid   = threadIdx.x;
    const int wr    = tid >> 5;          // warp = batch-within-block
    const int lid   = tid & 31;
    const int batch = blockIdx.x * 4 + wr;

    // X load issued first; weight staging overlaps its latency
    float4 xv = reinterpret_cast<const float4*>(X + batch * NT)[lid];

    for (int i = tid; i < NWTS; i += 128) {
        float v;
        if      (i < 24)  v = wk[i];
        else if (i < 48)  v = wq[i - 24];
        else if (i < 72)  v = wv[i - 48];
        else if (i < 96)  v = Wp[i - 72];
        else if (i < 99)  v = bp[i - 96];
        else if (i < 111) v = W1[i - 99];
        else if (i < 123) v = b1[i - 111];
        else if (i < 135) v = W2[i - 123];
        else if (i < 138) v = b2[i - 135];
        else if (i == 138) v = w_lm[0];
        else               v = b_lm[0];
        W[i] = v;
    }
    __syncthreads();   // the ONLY barrier in the kernel

    float x0 = xv.x, x1 = xv.y, x2 = xv.z, x3 = xv.w;

    #pragma unroll
    for (int l = 0; l < NL; ++l) {
        const float u0 = x0*x0, u1 = x1*x1, u2 = x2*x2, u3 = x3*x3;

        const float umx = redux_max_nn(fmaxf(fmaxf(u0, u1), fmaxf(u2, u3)));
        const float umn = redux_min_nn(fminf(fminf(u0, u1), fminf(u2, u3)));
        const float span = umx - umn;

        // all 8 heads' coefficients for this layer (smem reads, off critical path)
        float c8[NH], cf8[NH];
        float camax = 0.0f;
        #pragma unroll
        for (int h = 0; h < NH; ++h) {
            c8[h]  = W[O_WK + l*NH + h] * W[O_WQ + l*NH + h] * LOG2E;
            cf8[h] = W[O_WV + l*NH + h] * W[O_WP + l*NH + h];
            camax  = fmaxf(camax, fabsf(c8[h]));
        }

        float py0 = 0.f, py1 = 0.f, py2 = 0.f, py3 = 0.f;

        if (camax * span < 120.0f) {
            // ---- 8 heads in 2 groups of 4; each group = 8 parallel add-scan streams ----
            #pragma unroll
            for (int g = 0; g < 2; ++g) {
                float e0a[4], n0a[4], d01[4], m01[4], d012[4], m012[4], dT[4], mT[4], sd[4], sn[4];
                #pragma unroll
                for (int hh = 0; hh < 4; ++hh) {
                    const float ch = c8[g*4 + hh];
                    const float K  = ((ch > 0.0f) ? ch * umx : ch * umn) - 63.0f;
                    float e0 = ex2(fmaf(ch, u0, -K));
                    float e1 = ex2(fmaf(ch, u1, -K));
                    float e2 = ex2(fmaf(ch, u2, -K));
                    float e3 = ex2(fmaf(ch, u3, -K));
                    float n0 = e0*x0, n1 = e1*x1, n2 = e2*x2, n3 = e3*x3;
                    float a  = e0 + e1,  b_  = n0 + n1;
                    float a2 = a + e2,   b2_ = b_ + n2;
                    e0a[hh] = e0;  n0a[hh] = n0;
                    d01[hh] = a;   m01[hh] = b_;
                    d012[hh] = a2; m012[hh] = b2_;
                    dT[hh] = a2 + e3; mT[hh] = b2_ + n3;
                    sd[hh] = dT[hh];  sn[hh] = mT[hh];
                }
                #pragma unroll
                for (int o = 1; o < 32; o <<= 1) {
                    float ud[4], un[4];
                    #pragma unroll
                    for (int s = 0; s < 4; ++s) {
                        ud[s] = __shfl_up_sync(0xffffffffu, sd[s], o);
                        un[s] = __shfl_up_sync(0xffffffffu, sn[s], o);
                    }
                    if (lid >= o) {
                        #pragma unroll
                        for (int s = 0; s < 4; ++s) { sd[s] += ud[s]; sn[s] += un[s]; }
                    }
                }
                #pragma unroll
                for (int hh = 0; hh < 4; ++hh) {
                    const float cf = cf8[g*4 + hh];
                    float Pd = sd[hh] - dT[hh];
                    float Pn = sn[hh] - mT[hh];
                    // lane 0: Pn=Pd=0 -> 0/1e-37 = 0; elsewhere Pd >= 2^-57 >> 1e-37
                    float h0 = __fdividef(Pn, Pd + 1e-37f);
                    float h1 = __fdividef(Pn + n0a[hh],  Pd + e0a[hh]);
                    float h2 = __fdividef(Pn + m01[hh],  Pd + d01[hh]);
                    float h3 = __fdividef(Pn + m012[hh], Pd + d012[hh]);
                    py0 = fmaf(h0, cf, py0);
                    py1 = fmaf(h1, cf, py1);
                    py2 = fmaf(h2, cf, py2);
                    py3 = fmaf(h3, cf, py3);
                }
            }
        } else {
            // ---- exact monoid fallback, all 8 heads (rare) ----
            #pragma unroll
            for (int h = 0; h < NH; ++h) {
                float h0, h1, h2, h3;
                monoid_scan(c8[h], x0, x1, x2, x3, u0, u1, u2, u3, lid, h0, h1, h2, h3);
                py0 = fmaf(h0, cf8[h], py0);
                py1 = fmaf(h1, cf8[h], py1);
                py2 = fmaf(h2, cf8[h], py2);
                py3 = fmaf(h3, cf8[h], py3);
            }
        }

        // ---- fully in-warp epilogue: y, FF, next x (no barriers, no smem) ----
        const float bpv = W[O_BP + l];
        float y0 = py0 + bpv, y1 = py1 + bpv, y2 = py2 + bpv, y3 = py3 + bpv;

        const float b2v = W[O_B2 + l];
        float f0 = b2v, f1 = b2v, f2 = b2v, f3 = b2v;
        #pragma unroll
        for (int k = 0; k < 4; ++k) {
            const float w1v = W[O_W1 + l*4 + k];
            const float b1v = W[O_B1 + l*4 + k];
            const float w2v = W[O_W2 + l*4 + k];
            f0 = fmaf(fmaxf(fmaf(y0, w1v, b1v), 0.0f), w2v, f0);
            f1 = fmaf(fmaxf(fmaf(y1, w1v, b1v), 0.0f), w2v, f1);
            f2 = fmaf(fmaxf(fmaf(y2, w1v, b1v), 0.0f), w2v, f2);
            f3 = fmaf(fmaxf(fmaf(y3, w1v, b1v), 0.0f), w2v, f3);
        }
        x0 = y0 + f0; x1 = y1 + f1; x2 = y2 + f2; x3 = y3 + f3;
    }

    const float wlm = W[O_WLM], blm = W[O_BLM];
    float4 ov;
    ov.x = fmaf(x0, wlm, blm);
    ov.y = fmaf(x1, wlm, blm);
    ov.z = fmaf(x2, wlm, blm);
    ov.w = fmaf(x3, wlm, blm);
    reinterpret_cast<float4*>(out + batch * NT)[lid] = ov;
}

extern "C" void kernel_launch(void* const* d_in, const int* in_sizes, int n_in,
                              void* d_out, int out_size) {
    (void)in_sizes; (void)n_in; (void)out_size;
    cat_kernel<<<128, 128>>>(
        (const float*)d_in[0],  // X
        (const float*)d_in[1],  // wk
        (const float*)d_in[2],  // wq
        (const float*)d_in[3],  // wv
        (const float*)d_in[4],  // Wp
        (const float*)d_in[5],  // bp
        (const float*)d_in[6],  // W1
        (const float*)d_in[7],  // b1
        (const float*)d_in[8],  // W2
        (const float*)d_in[9],  // b2
        (const float*)d_in[10], // w_lm
        (const float*)d_in[11], // b_lm
        (float*)d_out);
}

// round 15
// speedup vs baseline: 1.2500x; 1.2500x over previous
#include <cuda_runtime.h>

#define NT 128
#define NH 8
#define NL 3
#define LOG2E 1.4426950408889634f

#define O_WK  0
#define O_WQ  24
#define O_WV  48
#define O_WP  72
#define O_BP  96
#define O_W1  99
#define O_B1  111
#define O_W2  123
#define O_B2  135
#define O_WLM 138
#define O_BLM 139
#define NWTS  140

__device__ __forceinline__ float ex2(float x) {
    float y;
    asm("ex2.approx.ftz.f32 %0, %1;" : "=f"(y) : "f"(x));
    return y;
}

__device__ __forceinline__ float redux_max_nn(float x) {
    unsigned r;
    asm("redux.sync.max.u32 %0, %1, 0xffffffff;" : "=r"(r) : "r"(__float_as_uint(x)));
    return __uint_as_float(r);
}
__device__ __forceinline__ float redux_min_nn(float x) {
    unsigned r;
    asm("redux.sync.min.u32 %0, %1, 0xffffffff;" : "=r"(r) : "r"(__float_as_uint(x)));
    return __uint_as_float(r);
}

struct OS { float m, d, n; };
__device__ __forceinline__ OS comb(OS a, OS b) {
    float mx = fmaxf(a.m, b.m);
    float mn = fminf(a.m, b.m);
    float e  = ex2(mn - mx);
    bool  bl = a.m < b.m;
    float sa = bl ? e : 1.0f;
    float sb = bl ? 1.0f : e;
    OS r; r.m = mx; r.d = fmaf(a.d, sa, b.d * sb); r.n = fmaf(a.n, sa, b.n * sb);
    return r;
}

__global__ __launch_bounds__(256) void cat_kernel(
    const float* __restrict__ X,
    const float* __restrict__ wk, const float* __restrict__ wq, const float* __restrict__ wv,
    const float* __restrict__ Wp, const float* __restrict__ bp,
    const float* __restrict__ W1, const float* __restrict__ b1,
    const float* __restrict__ W2, const float* __restrict__ b2,
    const float* __restrict__ w_lm, const float* __restrict__ b_lm,
    float* __restrict__ out)
{
    __shared__ float W[NWTS];
    __shared__ float ps[NH][NT];   // [warp=head][position] partial y
    __shared__ float xs[NT];       // x between layers

    const int tid   = threadIdx.x;
    const int wr    = tid >> 5;    // 0..7: head id
    const int lid   = tid & 31;
    const int batch = blockIdx.x;

    // X load first; weight staging overlaps the latency
    float4 xv = reinterpret_cast<const float4*>(X + batch * NT)[lid];

    if (tid < NWTS) {
        int i = tid;
        float v;
        if      (i < 24)  v = wk[i];
        else if (i < 48)  v = wq[i - 24];
        else if (i < 72)  v = wv[i - 48];
        else if (i < 96)  v = Wp[i - 72];
        else if (i < 99)  v = bp[i - 96];
        else if (i < 111) v = W1[i - 99];
        else if (i < 123) v = b1[i - 111];
        else if (i < 135) v = W2[i - 123];
        else if (i < 138) v = b2[i - 135];
        else if (i == 138) v = w_lm[0];
        else               v = b_lm[0];
        W[i] = v;
    }
    __syncthreads();

    // hoist this head's per-layer scan weights
    float c_r[NL], coef_r[NL], ca_r[NL];
    #pragma unroll
    for (int l = 0; l < NL; ++l) {
        float cc = W[O_WK + l*NH + wr] * W[O_WQ + l*NH + wr] * LOG2E;
        c_r[l]    = cc;
        ca_r[l]   = fabsf(cc);
        coef_r[l] = W[O_WV + l*NH + wr] * W[O_WP + l*NH + wr];
    }

    float x0 = xv.x, x1 = xv.y, x2 = xv.z, x3 = xv.w;

    #pragma unroll
    for (int l = 0; l < NL; ++l) {
        const float u0 = x0*x0, u1 = x1*x1, u2 = x2*x2, u3 = x3*x3;

        const float umx = redux_max_nn(fmaxf(fmaxf(u0, u1), fmaxf(u2, u3)));
        const float umn = redux_min_nn(fminf(fminf(u0, u1), fminf(u2, u3)));

        const float ch = c_r[l];
        const float cf = coef_r[l];

        float py0, py1, py2, py3;

        if (ca_r[l] * (umx - umn) < 120.0f) {
            // ---- single-window additive scan (terms >= 2^-57, no FTZ) ----
            const float K = ((ch > 0.0f) ? ch * umx : ch * umn) - 63.0f;
            float e0 = ex2(fmaf(ch, u0, -K));
            float e1 = ex2(fmaf(ch, u1, -K));
            float e2 = ex2(fmaf(ch, u2, -K));
            float e3 = ex2(fmaf(ch, u3, -K));
            float n0 = e0*x0, n1 = e1*x1, n2 = e2*x2, n3 = e3*x3;

            float d01 = e0 + e1, m01 = n0 + n1;
            float d012 = d01 + e2, m012 = m01 + n2;
            float dT = d012 + e3, mT = m012 + n3;

            float sd = dT, sn = mT;
            #pragma unroll
            for (int o = 1; o < 32; o <<= 1) {
                float ud = __shfl_up_sync(0xffffffffu, sd, o);
                float un = __shfl_up_sync(0xffffffffu, sn, o);
                if (lid >= o) { sd += ud; sn += un; }
            }
            float Pd = sd - dT;   // exclusive prefix by subtraction
            float Pn = sn - mT;

            float h0 = __fdividef(Pn, Pd + 1e-37f);   // lane0: 0/eps = 0
            float h1 = __fdividef(Pn + n0,   Pd + e0);
            float h2 = __fdividef(Pn + m01,  Pd + d01);
            float h3 = __fdividef(Pn + m012, Pd + d012);
            py0 = h0 * cf; py1 = h1 * cf; py2 = h2 * cf; py3 = h3 * cf;
        } else {
            // ---- exact monoid fallback ----
            OS a0 = { ch*u0, 1.0f, x0 };
            OS a1 = comb(a0, { ch*u1, 1.0f, x1 });
            OS a2 = comb(a1, { ch*u2, 1.0f, x2 });
            OS a3 = comb(a2, { ch*u3, 1.0f, x3 });
            OS agg = a3;
            #pragma unroll
            for (int o = 1; o < 32; o <<= 1) {
                OS up;
                up.m = __shfl_up_sync(0xffffffffu, agg.m, o);
                up.d = __shfl_up_sync(0xffffffffu, agg.d, o);
                up.n = __shfl_up_sync(0xffffffffu, agg.n, o);
                if (lid >= o) agg = comb(up, agg);
            }
            OS P;
            P.m = __shfl_up_sync(0xffffffffu, agg.m, 1);
            P.d = __shfl_up_sync(0xffffffffu, agg.d, 1);
            P.n = __shfl_up_sync(0xffffffffu, agg.n, 1);
            if (lid == 0) { P.m = -1e30f; P.d = 0.0f; P.n = 0.0f; }
            OS q1 = comb(P, a0);
            OS q2 = comb(P, a1);
            OS q3 = comb(P, a2);
            float h0 = (lid == 0) ? 0.0f : __fdividef(P.n, P.d);
            py0 = h0 * cf;
            py1 = __fdividef(q1.n, q1.d) * cf;
            py2 = __fdividef(q2.n, q2.d) * cf;
            py3 = __fdividef(q3.n, q3.d) * cf;
        }

        // ---- position-split epilogue ----
        reinterpret_cast<float4*>(ps[wr])[lid] = make_float4(py0, py1, py2, py3);
        __syncthreads();

        if (tid < NT) {
            const int p = tid;
            float y = W[O_BP + l];
            #pragma unroll
            for (int w = 0; w < NH; ++w) y += ps[w][p];

            float f = W[O_B2 + l];
            #pragma unroll
            for (int k = 0; k < 4; ++k)
                f = fmaf(fmaxf(fmaf(y, W[O_W1 + l*4 + k], W[O_B1 + l*4 + k]), 0.0f),
                         W[O_W2 + l*4 + k], f);
            float xn = y + f;

            if (l == NL - 1) {
                out[batch * NT + p] = fmaf(xn, W[O_WLM], W[O_BLM]);   // direct write, no final bar
            } else {
                xs[p] = xn;
            }
        }

        if (l < NL - 1) {
            __syncthreads();
            float4 xn = reinterpret_cast<const float4*>(xs)[lid];
            x0 = xn.x; x1 = xn.y; x2 = xn.z; x3 = xn.w;
        }
    }
}

extern "C" void kernel_launch(void* const* d_in, const int* in_sizes, int n_in,
                              void* d_out, int out_size) {
    (void)in_sizes; (void)n_in; (void)out_size;
    cat_kernel<<<512, 256>>>(
        (const float*)d_in[0],  // X
        (const float*)d_in[1],  // wk
        (const float*)d_in[2],  // wq
        (const float*)d_in[3],  // wv
        (const float*)d_in[4],  // Wp
        (const float*)d_in[5],  // bp
        (const float*)d_in[6],  // W1
        (const float*)d_in[7],  // b1
        (const float*)d_in[8],  // W2
        (const float*)d_in[9],  // b2
        (const float*)d_in[10], // w_lm
        (const float*)d_in[11], // b_lm
        (float*)d_out);
}